// round 9
// baseline (speedup 1.0000x reference)
#include <cuda_runtime.h>
#include <cstdint>

#define DIM    64
#define CODES  512
#define NTOK   262144
#define TPB    512
#define NBLK   2048            // NTOK / 128 tokens per block

// Output layout (float32, concatenated tuple)
#define OFF_Q    0L
#define OFF_QL   16777216L
#define OFF_IDX  16777217L
#define OFF_CL   17039361L
#define OFF_EMB  17039362L
#define OFF_N    17072130L
#define OFF_M    17072642L

// smem float offsets for vq_mma
#define SA_F     0          // A permuted: 16384 floats (64KB)
#define SB_F     16384      // B double buffer: 2 x 16384 floats (2 x 64KB)
#define SN_F     49152      // norms: 512
#define SXN_F    49664      // xnorm: 128
#define SRB_F    49792      // per-(token,cg) best: 512
#define SRI_F    50304      // per-(token,cg) idx: 512
#define SIDX_F   50816      // final per-token index: 128
#define SM_FLOATS 50944
#define SMEM_BYTES (SM_FLOATS * 4)   // 203776

__device__ float  g_embT[CODES * DIM];   // [c][d] fp32 for gather
__device__ float4 g_bperm[16384];        // packed tf32-split B fragments (hi,hi,lo,lo)
__device__ float  g_norm[CODES];
__device__ float  g_ni[CODES];
__device__ float  g_eofxT[CODES * DIM];  // [c][d]
__device__ float  g_loss;
__device__ int    g_idx[NTOK];
__device__ float  g_Ns[CODES];

// ---------------- helpers ----------------
__device__ __forceinline__ float tf32_rnd(float v) {
    uint32_t u; asm("cvt.rna.tf32.f32 %0, %1;" : "=r"(u) : "f"(v));
    return __uint_as_float(u);
}
__device__ __forceinline__ void red_f(float* p, float v) {
    asm volatile("red.global.add.f32 [%0], %1;" :: "l"(p), "f"(v) : "memory");
}
__device__ __forceinline__ void red_v2(float* p, float a, float b) {
    asm volatile("red.global.add.v2.f32 [%0], {%1, %2};" :: "l"(p), "f"(a), "f"(b) : "memory");
}
__device__ __forceinline__ void mma_tf32(float* d, const uint4 a, uint32_t b0, uint32_t b1) {
    asm("mma.sync.aligned.m16n8k8.row.col.f32.tf32.tf32.f32 "
        "{%0,%1,%2,%3}, {%4,%5,%6,%7}, {%8,%9}, {%0,%1,%2,%3};"
        : "+f"(d[0]), "+f"(d[1]), "+f"(d[2]), "+f"(d[3])
        : "r"(a.x), "r"(a.y), "r"(a.z), "r"(a.w), "r"(b0), "r"(b1));
}
__device__ __forceinline__ uint32_t smem_u32(const void* p) {
    uint32_t a;
    asm("{ .reg .u64 t; cvta.to.shared.u64 t, %1; cvt.u32.u64 %0, t; }" : "=r"(a) : "l"(p));
    return a;
}
__device__ __forceinline__ void cp16(uint32_t dst, const void* src) {
    asm volatile("cp.async.cg.shared.global [%0], [%1], 16;" :: "r"(dst), "l"(src) : "memory");
}
#define CP_COMMIT() asm volatile("cp.async.commit_group;" ::: "memory")

// ---------------- k1: zero + norms + transpose + packed tf32-split B ----------------
__global__ void vq_split(const float* __restrict__ emb) {
    const int idx = blockIdx.x * 512 + threadIdx.x;   // 0..32767

    g_eofxT[idx] = 0.f;
    if (idx < CODES) g_ni[idx] = 0.f;
    if (idx == 0) g_loss = 0.f;

    // transposed fp32 copy for gather
    { int c = idx >> 6, d = idx & 63; g_embT[idx] = emb[d * CODES + c]; }

    // exact code norms
    if (idx < CODES) {
        float s = 0.f;
        #pragma unroll
        for (int d = 0; d < DIM; d++) {
            float v = emb[d * CODES + idx];
            s = fmaf(v, v, s);
        }
        g_norm[idx] = s;
    }

    // packed B fragment slots: s = (((p*4+cg)*4+nf)*8+ks)*32 + l
    // float4 = {h(k0), h(k0+4), l(k0), l(k0+4)}
    if (idx < 16384) {
        int l  = idx & 31;
        int ks = (idx >> 5) & 7;
        int nf = (idx >> 8) & 3;
        int cg = (idx >> 10) & 3;
        int p  = idx >> 12;
        int code = p * 128 + cg * 32 + nf * 8 + (l >> 2);
        int k0 = ks * 8 + (l & 3);
        float v0 = emb[k0 * CODES + code];
        float v1 = emb[(k0 + 4) * CODES + code];
        float h0 = tf32_rnd(v0), h1 = tf32_rnd(v1);
        float4 o;
        o.x = h0; o.y = h1;
        o.z = tf32_rnd(v0 - h0); o.w = tf32_rnd(v1 - h1);
        g_bperm[idx] = o;
    }
}

// ---------------- k2: tensor-core assign (mma.sync tf32, 4-term split) ----------------
extern __shared__ float sm[];

__global__ void __launch_bounds__(TPB, 1)
vq_mma(const float* __restrict__ x, float* __restrict__ out) {
    const int tid  = threadIdx.x;
    const int lane = tid & 31, wid = tid >> 5;
    const int tg = wid & 3;          // token group (32 tokens)
    const int cg = wid >> 2;         // code group (32 codes per phase)
    const int g  = lane >> 2;        // mma groupID (row)
    const int tig = lane & 3;        // thread in group (col pair)

    float* sA  = sm + SA_F;
    float* sN  = sm + SN_F;
    float* sXn = sm + SXN_F;
    float* sRb = sm + SRB_F;
    int*   sRi = (int*)(sm + SRI_F);
    int*   sIdx = (int*)(sm + SIDX_F);
    const uint32_t smbase = smem_u32(sm);

    // norms to smem
    if (tid < CODES) sN[tid] = g_norm[tid];

    // ---- load x: thread owns (token = tid/4, quarter = tid&3) -> 16 floats ----
    const int tok = tid >> 2;
    const int q   = tid & 3;
    const int gtok0 = blockIdx.x * 128;
    float xv[16];
    {
        const float4* xg = (const float4*)(x + (size_t)(gtok0 + tok) * DIM + q * 16);
        #pragma unroll
        for (int j = 0; j < 4; j++) {
            float4 v = xg[j];
            xv[4*j] = v.x; xv[4*j+1] = v.y; xv[4*j+2] = v.z; xv[4*j+3] = v.w;
        }
    }
    // xnorm (quartet-combined; quartet is contiguous lanes)
    {
        float xn = 0.f;
        #pragma unroll
        for (int j = 0; j < 16; j++) xn = fmaf(xv[j], xv[j], xn);
        xn += __shfl_xor_sync(0xffffffffu, xn, 1);
        xn += __shfl_xor_sync(0xffffffffu, xn, 2);
        if (q == 0) sXn[tok] = xn;
    }
    // ---- write A permuted (tf32 split h/l) ----
    {
        const int ttg = tok >> 5, tmf = (tok >> 4) & 1, r = tok & 15;
        const int abase = (ttg * 2 + tmf) * 8;
        #pragma unroll
        for (int j = 0; j < 16; j++) {
            int k = q * 16 + j;
            int ks = k >> 3, kk = k & 7;
            int al = (r & 7) * 4 + (kk & 3);
            int ar = (r >> 3) | (((kk >> 2) & 1) << 1);
            float v = xv[j];
            float hf = tf32_rnd(v);
            float lf = tf32_rnd(v - hf);
            int base = ((abase + ks) * 2) * 128 + al * 4 + ar;
            sA[base] = hf;            // xt = 0 (hi)
            sA[base + 128] = lf;      // xt = 1 (lo)
        }
    }

    // ---- prologue: cp.async B phase 0 (64KB) ----
    {
        const char* src = (const char*)g_bperm;
        #pragma unroll
        for (int i = 0; i < 8; i++) {
            int off = (i * TPB + tid) * 16;
            cp16(smbase + (SB_F * 4) + off, src + off);
        }
        CP_COMMIT();
    }

    float best[4];  int bidx[4];
    #pragma unroll
    for (int s = 0; s < 4; s++) { best[s] = 3.402823466e38f; bidx[s] = 0; }

    for (int p = 0; p < 4; p++) {
        if (p < 3) {   // prefetch next phase into other buffer
            const char* src = (const char*)g_bperm + (p + 1) * 65536;
            uint32_t dst = smbase + (SB_F + ((p + 1) & 1) * 16384) * 4;
            #pragma unroll
            for (int i = 0; i < 8; i++) {
                int off = (i * TPB + tid) * 16;
                cp16(dst + off, src + off);
            }
            CP_COMMIT();
            asm volatile("cp.async.wait_group 1;" ::: "memory");
        } else {
            asm volatile("cp.async.wait_group 0;" ::: "memory");
        }
        __syncthreads();

        const float* bb = sm + SB_F + (p & 1) * 16384;
        float acc[2][4][4];
        #pragma unroll
        for (int mf = 0; mf < 2; mf++)
            #pragma unroll
            for (int nf = 0; nf < 4; nf++)
                #pragma unroll
                for (int qq = 0; qq < 4; qq++) acc[mf][nf][qq] = 0.f;

        #pragma unroll
        for (int ks = 0; ks < 8; ks++) {
            uint4 afr[2][2];
            #pragma unroll
            for (int mf = 0; mf < 2; mf++)
                #pragma unroll
                for (int xt = 0; xt < 2; xt++)
                    afr[mf][xt] = *(const uint4*)&sA[(((tg * 2 + mf) * 8 + ks) * 2 + xt) * 128 + lane * 4];
            uint4 bfr[4];
            #pragma unroll
            for (int nf = 0; nf < 4; nf++)
                bfr[nf] = *(const uint4*)&bb[((((cg * 4 + nf) * 8 + ks) * 32) + lane) * 4];
            #pragma unroll
            for (int xt = 0; xt < 2; xt++) {
                #pragma unroll
                for (int mf = 0; mf < 2; mf++) {
                    #pragma unroll
                    for (int nf = 0; nf < 4; nf++) {
                        mma_tf32(acc[mf][nf], afr[mf][xt], bfr[nf].x, bfr[nf].y);  // e hi
                        mma_tf32(acc[mf][nf], afr[mf][xt], bfr[nf].z, bfr[nf].w);  // e lo
                    }
                }
            }
        }

        // epilogue: dist + running argmin (codes ascending within thread)
        #pragma unroll
        for (int nf = 0; nf < 4; nf++) {
            int c0 = p * 128 + cg * 32 + nf * 8 + 2 * tig;
            float n0 = sN[c0], n1 = sN[c0 + 1];
            #pragma unroll
            for (int mf = 0; mf < 2; mf++) {
                float d00 = fmaf(-2.f, acc[mf][nf][0], n0);
                float d01 = fmaf(-2.f, acc[mf][nf][1], n1);
                float d10 = fmaf(-2.f, acc[mf][nf][2], n0);
                float d11 = fmaf(-2.f, acc[mf][nf][3], n1);
                int s0 = mf * 2, s1 = mf * 2 + 1;
                if (d00 < best[s0]) { best[s0] = d00; bidx[s0] = c0; }
                if (d01 < best[s0]) { best[s0] = d01; bidx[s0] = c0 + 1; }
                if (d10 < best[s1]) { best[s1] = d10; bidx[s1] = c0; }
                if (d11 < best[s1]) { best[s1] = d11; bidx[s1] = c0 + 1; }
            }
        }
        __syncthreads();
    }

    // reduce across tig lanes (same tokens), tie -> min index
    #pragma unroll
    for (int off = 1; off <= 2; off <<= 1) {
        #pragma unroll
        for (int s = 0; s < 4; s++) {
            float ob = __shfl_xor_sync(0xffffffffu, best[s], off);
            int   oc = __shfl_xor_sync(0xffffffffu, bidx[s], off);
            if (ob < best[s] || (ob == best[s] && oc < bidx[s])) { best[s] = ob; bidx[s] = oc; }
        }
    }
    if (tig == 0) {
        #pragma unroll
        for (int s = 0; s < 4; s++) {
            int mf = s >> 1, rh = s & 1;
            int t = tg * 32 + mf * 16 + g + rh * 8;
            sRb[t * 4 + cg] = best[s];
            sRi[t * 4 + cg] = bidx[s];
        }
    }
    __syncthreads();

    // combine code-groups + per-token outputs
    if (tid < 128) {
        float bd = sRb[tid * 4]; int bc = sRi[tid * 4];
        #pragma unroll
        for (int s = 1; s < 4; s++) {
            float ob = sRb[tid * 4 + s]; int oc = sRi[tid * 4 + s];
            if (ob < bd || (ob == bd && oc < bc)) { bd = ob; bc = oc; }
        }
        int gt = gtok0 + tid;
        g_idx[gt] = bc;
        out[OFF_IDX + gt] = (float)bc;
        red_f(&g_ni[bc], 1.0f);
        sIdx[tid] = bc;
        float l = bd + sXn[tid];
        #pragma unroll
        for (int o = 16; o; o >>= 1) l += __shfl_xor_sync(0xffffffffu, l, o);
        if ((tid & 31) == 0) red_f(&g_loss, l);
    }
    __syncthreads();

    // eofx scatter from x registers (thread's 16 dims)
    {
        int bc = sIdx[tok];
        float* gb = g_eofxT + bc * DIM + q * 16;
        #pragma unroll
        for (int j = 0; j < 8; j++) red_v2(gb + 2 * j, xv[2 * j], xv[2 * j + 1]);
    }
}

// ---------------- k3: quantize gather (warp per token group) ----------------
__global__ void __launch_bounds__(256)
vq_gather(float* __restrict__ out) {
    extern __shared__ float sE[];   // [512][64]
    const int tid = threadIdx.x;
    {
        const float4* src = (const float4*)g_embT;
        float4* dst = (float4*)sE;
        #pragma unroll
        for (int it = 0; it < 32; it++) dst[it * 256 + tid] = src[it * 256 + tid];
    }
    __syncthreads();
    const int warp = tid >> 5, lane = tid & 31;
    const int tbase = blockIdx.x * 1024 + warp * 128;
    int my[4];
    #pragma unroll
    for (int i = 0; i < 4; i++) my[i] = g_idx[tbase + i * 32 + lane];
    #pragma unroll
    for (int i = 0; i < 4; i++) {
        #pragma unroll 8
        for (int s = 0; s < 32; s++) {
            int c = __shfl_sync(0xffffffffu, my[i], s);
            float2 qv = *(const float2*)&sE[c * DIM + lane * 2];
            *(float2*)&out[OFF_Q + (size_t)(tbase + i * 32 + s) * DIM + lane * 2] = qv;
        }
    }
}

// ---------------- k4a: N_new, smoothing denom, losses ----------------
__global__ void vq_n(const float* __restrict__ Nin, float* __restrict__ out) {
    __shared__ float red[CODES];
    const int c = threadIdx.x;
    const float OMD = 1.0f - 0.99f;
    float Nn = fmaf(Nin[c], 0.99f, OMD * g_ni[c]);
    out[OFF_N + c] = Nn;
    red[c] = Nn;
    __syncthreads();
    for (int s = CODES / 2; s > 0; s >>= 1) {
        if (c < s) red[c] += red[c + s];
        __syncthreads();
    }
    float n = red[0];
    g_Ns[c] = (Nn + 1e-5f) / (n + CODES * 1e-5f) * n;
    if (c == 0) {
        float l = g_loss * (1.0f / 16777216.0f);
        out[OFF_QL] = l;
        out[OFF_CL] = l;
    }
}

// ---------------- k4b: M_new + embedding_new ----------------
__global__ void vq_m(const float* __restrict__ Min, float* __restrict__ out) {
    const int idx = blockIdx.x * 512 + threadIdx.x;   // 32768
    const int d = idx >> 9, c = idx & (CODES - 1);
    const float OMD = 1.0f - 0.99f;
    float Mn = fmaf(Min[idx], 0.99f, OMD * g_eofxT[c * DIM + d]);
    out[OFF_M + idx] = Mn;
    out[OFF_EMB + idx] = Mn / g_Ns[c];
}

extern "C" void kernel_launch(void* const* d_in, const int* in_sizes, int n_in,
                              void* d_out, int out_size) {
    const float* x   = (const float*)d_in[0];
    const float* emb = (const float*)d_in[1];
    const float* N   = (const float*)d_in[2];
    const float* M   = (const float*)d_in[3];
    float* out = (float*)d_out;

    cudaFuncSetAttribute(vq_mma, cudaFuncAttributeMaxDynamicSharedMemorySize, SMEM_BYTES);
    cudaFuncSetAttribute(vq_gather, cudaFuncAttributeMaxDynamicSharedMemorySize, 131072);

    vq_split<<<64, 512>>>(emb);
    vq_mma<<<NBLK, TPB, SMEM_BYTES>>>(x, out);
    vq_gather<<<256, 256, 131072>>>(out);
    vq_n<<<1, CODES>>>(N, out);
    vq_m<<<64, 512>>>(M, out);
}

// round 10
// speedup vs baseline: 1.1154x; 1.1154x over previous
#include <cuda_runtime.h>
#include <cuda_fp16.h>
#include <cstdint>

#define DIM    64
#define CODES  512
#define NTOK   262144
#define TPB    256
#define BLKTOK 256
#define NBLK   (NTOK / BLKTOK)   // 1024

// Output layout (float32, concatenated tuple)
#define OFF_Q    0L
#define OFF_QL   16777216L
#define OFF_IDX  16777217L
#define OFF_CL   17039361L
#define OFF_EMB  17039362L
#define OFF_N    17072130L
#define OFF_M    17072642L

// vq_mma smem byte offsets
#define SMB_A    0          // A permuted fp16: 64KB (128 slots x 512B)
#define SMB_B    65536      // B double buffer: 2 x 32KB
#define SMB_N    131072     // norms: 512 f
#define SMB_XN   133120     // xnorm: 256 f
#define SMB_RB   134144     // best: 512 f
#define SMB_RI   136192     // idx: 512 i
#define SMEM_BYTES 138240

__device__ float  g_embT[CODES * DIM];   // [c][d] fp32 for gather
__device__ uint4  g_bperm[8192];         // packed fp16-split B fragments (hi,hi,lo,lo)
__device__ float  g_norm[CODES];
__device__ float  g_ni[CODES];
__device__ float  g_eofxT[CODES * DIM];  // [c][d]
__device__ float  g_loss;
__device__ int    g_idx[NTOK];
__device__ float  g_Ns[CODES];

// ---------------- helpers ----------------
__device__ __forceinline__ void red_f(float* p, float v) {
    asm volatile("red.global.add.f32 [%0], %1;" :: "l"(p), "f"(v) : "memory");
}
__device__ __forceinline__ void red_v2(float* p, float a, float b) {
    asm volatile("red.global.add.v2.f32 [%0], {%1, %2};" :: "l"(p), "f"(a), "f"(b) : "memory");
}
__device__ __forceinline__ void mma_f16(float* d, const uint4 a, uint32_t b0, uint32_t b1) {
    asm("mma.sync.aligned.m16n8k16.row.col.f32.f16.f16.f32 "
        "{%0,%1,%2,%3}, {%4,%5,%6,%7}, {%8,%9}, {%0,%1,%2,%3};"
        : "+f"(d[0]), "+f"(d[1]), "+f"(d[2]), "+f"(d[3])
        : "r"(a.x), "r"(a.y), "r"(a.z), "r"(a.w), "r"(b0), "r"(b1));
}
__device__ __forceinline__ uint32_t smem_u32(const void* p) {
    uint32_t a;
    asm("{ .reg .u64 t; cvta.to.shared.u64 t, %1; cvt.u32.u64 %0, t; }" : "=r"(a) : "l"(p));
    return a;
}
__device__ __forceinline__ void cp16(uint32_t dst, const void* src) {
    asm volatile("cp.async.cg.shared.global [%0], [%1], 16;" :: "r"(dst), "l"(src) : "memory");
}
#define CP_COMMIT() asm volatile("cp.async.commit_group;" ::: "memory")

__device__ __forceinline__ uint32_t pack2(float a, float b) {
    __half2 h = __halves2half2(__float2half_rn(a), __float2half_rn(b));
    return *reinterpret_cast<uint32_t*>(&h);
}
__device__ __forceinline__ void split1(float v, __half& h, __half& l) {
    h = __float2half_rn(v);
    l = __float2half_rn(v - __half2float(h));
}

// ---------------- k1: zero + norms + transpose + packed fp16-split B ----------------
__global__ void vq_split(const float* __restrict__ emb) {
    const int idx = blockIdx.x * 512 + threadIdx.x;   // 0..32767

    g_eofxT[idx] = 0.f;
    if (idx < CODES) g_ni[idx] = 0.f;
    if (idx == 0) g_loss = 0.f;

    // transposed fp32 copy for gather
    { int c = idx >> 6, d = idx & 63; g_embT[idx] = emb[d * CODES + c]; }

    // exact code norms
    if (idx < CODES) {
        float s = 0.f;
        #pragma unroll
        for (int d = 0; d < DIM; d++) {
            float v = emb[d * CODES + idx];
            s = fmaf(v, v, s);
        }
        g_norm[idx] = s;
    }

    // B fragment slots: idx = (((p*2+cg)*8+nf)*4+ks)*32 + lane
    // uint4 = {b0_hi, b1_hi, b0_lo, b1_lo}, each fp16x2
    if (idx < 8192) {
        int l  = idx & 31;
        int ks = (idx >> 5) & 3;
        int nf = (idx >> 7) & 7;
        int cg = (idx >> 10) & 1;
        int p  = idx >> 11;
        int n  = p * 128 + cg * 64 + nf * 8 + (l >> 2);
        int k0 = ks * 16 + 2 * (l & 3);
        float v00 = emb[k0 * CODES + n];
        float v01 = emb[(k0 + 1) * CODES + n];
        float v10 = emb[(k0 + 8) * CODES + n];
        float v11 = emb[(k0 + 9) * CODES + n];
        __half h00, l00, h01, l01, h10, l10, h11, l11;
        split1(v00, h00, l00); split1(v01, h01, l01);
        split1(v10, h10, l10); split1(v11, h11, l11);
        uint4 o;
        { __half2 t = __halves2half2(h00, h01); o.x = *reinterpret_cast<uint32_t*>(&t); }
        { __half2 t = __halves2half2(h10, h11); o.y = *reinterpret_cast<uint32_t*>(&t); }
        { __half2 t = __halves2half2(l00, l01); o.z = *reinterpret_cast<uint32_t*>(&t); }
        { __half2 t = __halves2half2(l10, l11); o.w = *reinterpret_cast<uint32_t*>(&t); }
        g_bperm[idx] = o;
    }
}

// ---------------- k2: fp16 4-term split mma.sync assign ----------------
extern __shared__ char sm[];

__global__ void __launch_bounds__(TPB, 1)
vq_mma(const float* __restrict__ x, float* __restrict__ out) {
    const int tid  = threadIdx.x;
    const int lane = tid & 31, wid = tid >> 5;
    const int tg = wid & 3;          // token group (64 tokens)
    const int cg = wid >> 2;         // code group (64 codes / phase)
    const int g  = lane >> 2;
    const int tig = lane & 3;

    float* sN  = (float*)(sm + SMB_N);
    float* sXn = (float*)(sm + SMB_XN);
    float* sRb = (float*)(sm + SMB_RB);
    int*   sRi = (int*)(sm + SMB_RI);
    const uint32_t smbase = smem_u32(sm);

    if (tid < 256) { sN[tid] = g_norm[tid]; sN[256 + tid] = g_norm[256 + tid]; }

    const int gtok0 = blockIdx.x * BLKTOK;
    // ---- load own token, compute xnorm, write permuted A (fp16 split) ----
    {
        const int T = tid;
        const int ttg = T >> 6, r = T & 63;
        const int mf = r >> 4, rr = r & 15;
        const int gg = rr & 7, row8 = rr >> 3;
        const uint32_t lanebase = (uint32_t)((gg * 4) * 16);   // + tig*16 later per k
        const float4* xg = (const float4*)(x + (size_t)(gtok0 + T) * DIM);
        float xn = 0.f;
        #pragma unroll
        for (int j = 0; j < 16; j++) {   // float4 = k 4j..4j+3 (two k-pairs)
            float4 v = xg[j];
            xn = fmaf(v.x, v.x, xn); xn = fmaf(v.y, v.y, xn);
            xn = fmaf(v.z, v.z, xn); xn = fmaf(v.w, v.w, xn);
            #pragma unroll
            for (int pp = 0; pp < 2; pp++) {
                int k = 4 * j + 2 * pp;
                float a = pp ? v.z : v.x;
                float b = pp ? v.w : v.y;
                int ks = k >> 4, kk = k & 15;
                int sel8 = kk >> 3, ktig = (kk & 7) >> 1;
                int areg = sel8 * 2 + row8;
                __half ha, la, hb, lb;
                split1(a, ha, la); split1(b, hb, lb);
                int slot = ((ttg * 4 + mf) * 4 + ks) * 2;
                uint32_t byte = (uint32_t)slot * 512 + lanebase + (uint32_t)ktig * 16 + (uint32_t)areg * 4;
                __half2 hh = __halves2half2(ha, hb);
                __half2 ll = __halves2half2(la, lb);
                *(uint32_t*)(sm + SMB_A + byte)       = *reinterpret_cast<uint32_t*>(&hh);
                *(uint32_t*)(sm + SMB_A + byte + 512) = *reinterpret_cast<uint32_t*>(&ll);
            }
        }
        sXn[T] = xn;
    }

    // ---- prologue: cp.async B phase 0 (32KB) ----
    {
        const char* src = (const char*)g_bperm;
        #pragma unroll
        for (int i = 0; i < 8; i++) {
            int off = (i * TPB + tid) * 16;
            cp16(smbase + SMB_B + off, src + off);
        }
        CP_COMMIT();
    }

    float best[8];  int bidx[8];
    #pragma unroll
    for (int s = 0; s < 8; s++) { best[s] = 3.402823466e38f; bidx[s] = 0; }

    for (int p = 0; p < 4; p++) {
        if (p < 3) {
            const char* src = (const char*)g_bperm + (p + 1) * 32768;
            uint32_t dst = smbase + SMB_B + ((p + 1) & 1) * 32768;
            #pragma unroll
            for (int i = 0; i < 8; i++) {
                int off = (i * TPB + tid) * 16;
                cp16(dst + off, src + off);
            }
            CP_COMMIT();
            asm volatile("cp.async.wait_group 1;" ::: "memory");
        } else {
            asm volatile("cp.async.wait_group 0;" ::: "memory");
        }
        __syncthreads();

        const char* bb = sm + SMB_B + (p & 1) * 32768;

        #pragma unroll
        for (int ch = 0; ch < 2; ch++) {
            float acc[4][4][4];
            #pragma unroll
            for (int mf = 0; mf < 4; mf++)
                #pragma unroll
                for (int j = 0; j < 4; j++)
                    #pragma unroll
                    for (int q = 0; q < 4; q++) acc[mf][j][q] = 0.f;

            #pragma unroll
            for (int ks = 0; ks < 4; ks++) {
                uint4 af[4][2];
                #pragma unroll
                for (int mf = 0; mf < 4; mf++)
                    #pragma unroll
                    for (int hl = 0; hl < 2; hl++)
                        af[mf][hl] = *(const uint4*)(sm + SMB_A +
                            (((tg * 4 + mf) * 4 + ks) * 2 + hl) * 512 + lane * 16);
                uint4 bf[4];
                #pragma unroll
                for (int j = 0; j < 4; j++)
                    bf[j] = *(const uint4*)(bb +
                        ((cg * 8 + ch * 4 + j) * 4 + ks) * 512 + lane * 16);
                #pragma unroll
                for (int mf = 0; mf < 4; mf++) {
                    #pragma unroll
                    for (int j = 0; j < 4; j++) {
                        mma_f16(acc[mf][j], af[mf][0], bf[j].x, bf[j].y);  // xh·eh
                        mma_f16(acc[mf][j], af[mf][0], bf[j].z, bf[j].w);  // xh·el
                        mma_f16(acc[mf][j], af[mf][1], bf[j].x, bf[j].y);  // xl·eh
                        mma_f16(acc[mf][j], af[mf][1], bf[j].z, bf[j].w);  // xl·el
                    }
                }
            }
            // epilogue chunk: dist + running argmin (codes ascending)
            #pragma unroll
            for (int j = 0; j < 4; j++) {
                int c0 = p * 128 + cg * 64 + (ch * 4 + j) * 8 + 2 * tig;
                float n0 = sN[c0], n1 = sN[c0 + 1];
                #pragma unroll
                for (int mf = 0; mf < 4; mf++) {
                    float d00 = fmaf(-2.f, acc[mf][j][0], n0);
                    float d01 = fmaf(-2.f, acc[mf][j][1], n1);
                    float d10 = fmaf(-2.f, acc[mf][j][2], n0);
                    float d11 = fmaf(-2.f, acc[mf][j][3], n1);
                    int s0 = mf * 2, s1 = mf * 2 + 1;
                    if (d00 < best[s0]) { best[s0] = d00; bidx[s0] = c0; }
                    if (d01 < best[s0]) { best[s0] = d01; bidx[s0] = c0 + 1; }
                    if (d10 < best[s1]) { best[s1] = d10; bidx[s1] = c0; }
                    if (d11 < best[s1]) { best[s1] = d11; bidx[s1] = c0 + 1; }
                }
            }
        }
        __syncthreads();
    }

    // reduce across tig lanes (same tokens), tie -> min index
    #pragma unroll
    for (int off = 1; off <= 2; off <<= 1) {
        #pragma unroll
        for (int s = 0; s < 8; s++) {
            float ob = __shfl_xor_sync(0xffffffffu, best[s], off);
            int   oc = __shfl_xor_sync(0xffffffffu, bidx[s], off);
            if (ob < best[s] || (ob == best[s] && oc < bidx[s])) { best[s] = ob; bidx[s] = oc; }
        }
    }
    if (tig == 0) {
        #pragma unroll
        for (int s = 0; s < 8; s++) {
            int mf = s >> 1, rh = s & 1;
            int t = tg * 64 + mf * 16 + rh * 8 + g;
            sRb[t * 2 + cg] = best[s];
            sRi[t * 2 + cg] = bidx[s];
        }
    }
    __syncthreads();

    // per-token tail: combine cg, outputs, loss, eofx (reload x)
    {
        const int t = tid;
        float b0 = sRb[t * 2];     int i0 = sRi[t * 2];
        float b1 = sRb[t * 2 + 1]; int i1 = sRi[t * 2 + 1];
        int bc; float bd;
        if (b1 < b0 || (b1 == b0 && i1 < i0)) { bc = i1; bd = b1; } else { bc = i0; bd = b0; }
        const int gt = gtok0 + t;
        g_idx[gt] = bc;
        out[OFF_IDX + gt] = (float)bc;
        red_f(&g_ni[bc], 1.0f);
        float l = bd + sXn[t];
        #pragma unroll
        for (int o = 16; o; o >>= 1) l += __shfl_xor_sync(0xffffffffu, l, o);
        if ((tid & 31) == 0) red_f(&g_loss, l);

        float* gb = g_eofxT + bc * DIM;
        const float4* xg = (const float4*)(x + (size_t)gt * DIM);
        #pragma unroll
        for (int j = 0; j < 16; j++) {
            float4 v = xg[j];
            red_v2(gb + 4 * j, v.x, v.y);
            red_v2(gb + 4 * j + 2, v.z, v.w);
        }
    }
}

// ---------------- k3: quantize gather (warp per token group) ----------------
__global__ void __launch_bounds__(256)
vq_gather(float* __restrict__ out) {
    extern __shared__ float sE[];   // [512][64]
    const int tid = threadIdx.x;
    {
        const float4* src = (const float4*)g_embT;
        float4* dst = (float4*)sE;
        #pragma unroll
        for (int it = 0; it < 32; it++) dst[it * 256 + tid] = src[it * 256 + tid];
    }
    __syncthreads();
    const int warp = tid >> 5, lane = tid & 31;
    const int tbase = blockIdx.x * 1024 + warp * 128;
    int my[4];
    #pragma unroll
    for (int i = 0; i < 4; i++) my[i] = g_idx[tbase + i * 32 + lane];
    #pragma unroll
    for (int i = 0; i < 4; i++) {
        #pragma unroll 8
        for (int s = 0; s < 32; s++) {
            int c = __shfl_sync(0xffffffffu, my[i], s);
            float2 qv = *(const float2*)&sE[c * DIM + lane * 2];
            *(float2*)&out[OFF_Q + (size_t)(tbase + i * 32 + s) * DIM + lane * 2] = qv;
        }
    }
}

// ---------------- k4a: N_new, smoothing denom, losses ----------------
__global__ void vq_n(const float* __restrict__ Nin, float* __restrict__ out) {
    __shared__ float red[CODES];
    const int c = threadIdx.x;
    const float OMD = 1.0f - 0.99f;
    float Nn = fmaf(Nin[c], 0.99f, OMD * g_ni[c]);
    out[OFF_N + c] = Nn;
    red[c] = Nn;
    __syncthreads();
    for (int s = CODES / 2; s > 0; s >>= 1) {
        if (c < s) red[c] += red[c + s];
        __syncthreads();
    }
    float n = red[0];
    g_Ns[c] = (Nn + 1e-5f) / (n + CODES * 1e-5f) * n;
    if (c == 0) {
        float l = g_loss * (1.0f / 16777216.0f);
        out[OFF_QL] = l;
        out[OFF_CL] = l;
    }
}

// ---------------- k4b: M_new + embedding_new ----------------
__global__ void vq_m(const float* __restrict__ Min, float* __restrict__ out) {
    const int idx = blockIdx.x * 512 + threadIdx.x;   // 32768
    const int d = idx >> 9, c = idx & (CODES - 1);
    const float OMD = 1.0f - 0.99f;
    float Mn = fmaf(Min[idx], 0.99f, OMD * g_eofxT[c * DIM + d]);
    out[OFF_M + idx] = Mn;
    out[OFF_EMB + idx] = Mn / g_Ns[c];
}

extern "C" void kernel_launch(void* const* d_in, const int* in_sizes, int n_in,
                              void* d_out, int out_size) {
    const float* x   = (const float*)d_in[0];
    const float* emb = (const float*)d_in[1];
    const float* N   = (const float*)d_in[2];
    const float* M   = (const float*)d_in[3];
    float* out = (float*)d_out;

    cudaFuncSetAttribute(vq_mma, cudaFuncAttributeMaxDynamicSharedMemorySize, SMEM_BYTES);
    cudaFuncSetAttribute(vq_gather, cudaFuncAttributeMaxDynamicSharedMemorySize, 131072);

    vq_split<<<64, 512>>>(emb);
    vq_mma<<<NBLK, TPB, SMEM_BYTES>>>(x, out);
    vq_gather<<<256, 256, 131072>>>(out);
    vq_n<<<1, CODES>>>(N, out);
    vq_m<<<64, 512>>>(M, out);
}